// round 16
// baseline (speedup 1.0000x reference)
#include <cuda_runtime.h>
#include <cstdint>

// Fixed shapes: B=32, T=1024, D=1024. All GEMM paths are dead code:
// softmax over a singleton axis => every attention weight == 1.0, so
//   context[b,d] = sum_t values[b,t,d],  aw = 1.0,  cov[b,t] = t.
#define BB 32
#define TT 1024
#define DD 1024
#define D4 256                       // float4 per row (4KB rows)
#define NCHUNK 32                    // chunks per batch (CTAs per batch)
#define TC (TT / NCHUNK)             // 32 rows per chunk (128KB contiguous)

// Output layout (98304 floats):
//   [0, B*D)             context   (written once by the last CTA per batch)
//   [B*D, B*D+B*T)       attention_weights (all 1.0)
//   [B*D+B*T, end)       coverage (cov[b,t] = t)

__device__ float4 g_partial[BB * NCHUNK * D4];   // 4 MB scratch
// Monotonic per-batch tickets (zero-init at load; epoch arithmetic -> no reset
// needed across graph replays). Stride 32 -> one counter per 128B line.
__device__ unsigned int g_tick[BB * 32];

// ---- Single kernel: proven stream + last-CTA-per-batch in-kernel reduce ----
// Stream = R4's measured-21.4us shape: 1024 slim CTAs, contiguous 128KB each,
// thread-per-float4-column, 8 independent __ldcs loads in flight, plain STG
// of the 4KB partial. Epilogue = classic threadfence-reduction, but with the
// fence on tid0 ONLY (R3's all-thread fence was the 5us mistake).
__global__ __launch_bounds__(256) void fused_kernel(const float4* __restrict__ vals,
                                                    float* __restrict__ out) {
    const int c   = blockIdx.x;      // 0..31 chunk
    const int b   = blockIdx.y;      // 0..31 batch
    const int tid = threadIdx.x;     // 0..255 (one float4 column)

    // ---- Stream: contiguous 128KB, 8-deep independent __ldcs loads ----
    const float4* __restrict__ p = vals + ((size_t)b * TT + (size_t)c * TC) * D4 + tid;

    float x = 0.f, y = 0.f, z = 0.f, w = 0.f;
#pragma unroll
    for (int i = 0; i < TC / 8; ++i) {
        float4 v0 = __ldcs(&p[0 * (size_t)D4]);
        float4 v1 = __ldcs(&p[1 * (size_t)D4]);
        float4 v2 = __ldcs(&p[2 * (size_t)D4]);
        float4 v3 = __ldcs(&p[3 * (size_t)D4]);
        float4 v4 = __ldcs(&p[4 * (size_t)D4]);
        float4 v5 = __ldcs(&p[5 * (size_t)D4]);
        float4 v6 = __ldcs(&p[6 * (size_t)D4]);
        float4 v7 = __ldcs(&p[7 * (size_t)D4]);
        p += 8 * (size_t)D4;
        x += v0.x; y += v0.y; z += v0.z; w += v0.w;
        x += v1.x; y += v1.y; z += v1.z; w += v1.w;
        x += v2.x; y += v2.y; z += v2.z; w += v2.w;
        x += v3.x; y += v3.y; z += v3.z; w += v3.w;
        x += v4.x; y += v4.y; z += v4.z; w += v4.w;
        x += v5.x; y += v5.y; z += v5.z; w += v5.w;
        x += v6.x; y += v6.y; z += v6.z; w += v6.w;
        x += v7.x; y += v7.y; z += v7.z; w += v7.w;
    }
    g_partial[(b * NCHUNK + c) * D4 + tid] = make_float4(x, y, z, w);

    // aw/cov fill: 1024 blocks x 8 float4 per array (hidden in the stream).
    const int blk = b * NCHUNK + c;  // 0..1023
    if (tid >= 64 && tid < 72) {
        float4* aw4 = reinterpret_cast<float4*>(out + BB * DD);
        aw4[blk * 8 + (tid - 64)] = make_float4(1.f, 1.f, 1.f, 1.f);
    } else if (tid >= 96 && tid < 104) {
        float4* cov4 = reinterpret_cast<float4*>(out + BB * DD + BB * TT);
        const int q = blk * 8 + (tid - 96);      // float4 index into [B,T]
        const int t0 = (q * 4) & (TT - 1);
        cov4[q] = make_float4((float)t0, (float)(t0 + 1), (float)(t0 + 2), (float)(t0 + 3));
    }

    // ---- Ticket: classic threadfence-reduction handshake (tid0 only) ----
    __shared__ bool is_last;
    __syncthreads();                 // all partial STGs issued (block-ordered)
    if (tid == 0) {
        __threadfence();             // release: this block's partial visible
        unsigned int t = atomicAdd(&g_tick[b * 32], 1u);
        is_last = ((t & (NCHUNK - 1u)) == (NCHUNK - 1u));   // epoch-safe
    }
    __syncthreads();

    if (!is_last) return;            // 31 of 32 CTAs exit immediately

    // ---- Last CTA of this batch: fixed-order reduce of all 32 partials ----
    __threadfence();                 // acquire: peers' partials visible
    const float4* part = g_partial + (size_t)b * NCHUNK * D4 + tid;
    float X = 0.f, Y = 0.f, Z = 0.f, W = 0.f;
#pragma unroll
    for (int cc = 0; cc < NCHUNK; ++cc) {        // fixed order -> deterministic
        float4 v = __ldcg(&part[(size_t)cc * D4]);
        X += v.x; Y += v.y; Z += v.z; W += v.w;
    }
    reinterpret_cast<float4*>(out)[(size_t)b * D4 + tid] = make_float4(X, Y, Z, W);
}

extern "C" void kernel_launch(void* const* d_in, const int* in_sizes, int n_in,
                              void* d_out, int out_size) {
    // Inputs: query, values, W1, b1, W2, b2, W3, b3, V, bV
    const float4* values = (const float4*)d_in[1];
    float* out = (float*)d_out;

    dim3 grid1(NCHUNK, BB);                      // 1024 blocks, one wave
    fused_kernel<<<grid1, D4>>>(values, out);
}